// round 13
// baseline (speedup 1.0000x reference)
#include <cuda_runtime.h>
#include <cuda_fp16.h>

#define L 2048
#define CIN 16
#define GROUPS 4
#define LS 2056              // padded scratch row stride in HALVES: 4 lead + 2048 + 4 trail
#define ROWS_P (L + 2)       // +1 zero guard row above and below per channel

// ~135 MiB fp16 scratch. Channel c, padded row r holds data row r-1 (rows 0
// and L+1 zero guards). Cols: [0,4) lead pad, [4,4+L) data, trail pad.
// Above-diagonal cols zero-filled through the last 512-tile any conv consumer
// reads, so conv staging is fully branch-free.
__device__ __half g_probs[(size_t)CIN * ROWS_P * LS];

__device__ __forceinline__ void fma2(unsigned long long& d,
                                     unsigned long long a, unsigned long long b) {
    asm("fma.rn.f32x2 %0, %1, %2, %0;" : "+l"(d) : "l"(a), "l"(b));
}
__device__ __forceinline__ unsigned long long pk2(float a, float b) {
    unsigned long long r;
    asm("mov.b64 %0, {%1, %2};" : "=l"(r) : "f"(a), "f"(b));
    return r;
}
__device__ __forceinline__ void upk2(unsigned long long p, float& a, float& b) {
    asm("mov.b64 {%0, %1}, %2;" : "=f"(a), "=f"(b) : "l"(p));
}

// ---------------------------------------------------------------------------
// Kernel 1: causal sparsemax, ONE WARP PER ROW. (unchanged R9 winner)
// ---------------------------------------------------------------------------
__global__ void __launch_bounds__(256) sparsemax_rows(const float* __restrict__ scores) {
    const int tid  = threadIdx.x;
    const int w    = tid >> 5;
    const int lane = tid & 31;
    const int i    = (blockIdx.x << 3) + w;
    const int c    = blockIdx.y;
    const int n    = i + 1;

    const float* src = scores + ((size_t)c * L + (size_t)i) * L;
    __half* dst = g_probs + ((size_t)c * ROWS_P + (size_t)(i + 1)) * LS + 4;

    const int full = n >> 7;
    const int base = lane << 2;

    float z[64];
#pragma unroll
    for (int t = 0; t < 16; t++) {
        if (t <= full) {
            *reinterpret_cast<float4*>(&z[4 * t]) =
                *reinterpret_cast<const float4*>(src + (t << 7) + base);
        }
    }
#pragma unroll
    for (int t = 0; t < 16; t++) {
        if (t == full) {
#pragma unroll
            for (int q = 0; q < 4; q++)
                if ((t << 7) + base + q >= n) z[4 * t + q] = -3.0e38f;
        }
    }

    float S = 0.f, M = -3.0e38f;
#pragma unroll
    for (int t = 0; t < 16; t++) {
        if (t > full) break;
#pragma unroll
        for (int q = 0; q < 4; q++) {
            float zz = z[4 * t + q];
            if (zz > -3.0e38f) S += zz;
            M = fmaxf(M, zz);
        }
    }
#pragma unroll
    for (int o = 16; o; o >>= 1) {
        S += __shfl_xor_sync(0xffffffffu, S, o);
        M = fmaxf(M, __shfl_xor_sync(0xffffffffu, M, o));
    }

    float tau = fmaxf((S - 1.0f) / (float)n, M - 1.0f);
    float kprev = 3.0e38f;

#pragma unroll 1
    for (int it = 0; it < 64; ++it) {
        float ls = 0.f, lc = 0.f;
#pragma unroll
        for (int t = 0; t < 16; t++) {
            if (t > full) break;
#pragma unroll
            for (int q = 0; q < 4; q++) {
                float zz = z[4 * t + q];
                if (zz > tau) { ls += zz; lc += 1.f; }
            }
        }
#pragma unroll
        for (int o = 16; o; o >>= 1) {
            ls += __shfl_xor_sync(0xffffffffu, ls, o);
            lc += __shfl_xor_sync(0xffffffffu, lc, o);
        }
        if (lc >= kprev || lc == 0.f) break;
        tau = (ls - 1.0f) / lc;
        kprev = lc;
    }

    const int E  = min(2052, ((((n + 1) >> 9) << 9) + 516));
    const int EC = (E + 127) >> 7;
#pragma unroll
    for (int t = 0; t < 16; t++) {
        if (t < full) {
            __half2 h0 = __floats2half2_rn(fmaxf(z[4 * t + 0] - tau, 0.f),
                                           fmaxf(z[4 * t + 1] - tau, 0.f));
            __half2 h1 = __floats2half2_rn(fmaxf(z[4 * t + 2] - tau, 0.f),
                                           fmaxf(z[4 * t + 3] - tau, 0.f));
            uint2 pk;
            pk.x = *reinterpret_cast<unsigned*>(&h0);
            pk.y = *reinterpret_cast<unsigned*>(&h1);
            *reinterpret_cast<uint2*>(dst + (t << 7) + base) = pk;
        } else if (t == full) {
            float p0 = ((t << 7) + base + 0 < n) ? fmaxf(z[4 * t + 0] - tau, 0.f) : 0.f;
            float p1 = ((t << 7) + base + 1 < n) ? fmaxf(z[4 * t + 1] - tau, 0.f) : 0.f;
            float p2 = ((t << 7) + base + 2 < n) ? fmaxf(z[4 * t + 2] - tau, 0.f) : 0.f;
            float p3 = ((t << 7) + base + 3 < n) ? fmaxf(z[4 * t + 3] - tau, 0.f) : 0.f;
            __half2 h0 = __floats2half2_rn(p0, p1);
            __half2 h1 = __floats2half2_rn(p2, p3);
            uint2 pk;
            pk.x = *reinterpret_cast<unsigned*>(&h0);
            pk.y = *reinterpret_cast<unsigned*>(&h1);
            *reinterpret_cast<uint2*>(dst + (t << 7) + base) = pk;
        } else if (t < EC) {
            *reinterpret_cast<uint2*>(dst + (t << 7) + base) = make_uint2(0u, 0u);
        }
    }
    if (lane == 0) {
        *reinterpret_cast<uint2*>(dst - 4) = make_uint2(0u, 0u);
        if (E > 2048) *reinterpret_cast<uint2*>(dst + 2048) = make_uint2(0u, 0u);
    }
    if (i == 0) {
        uint4* gr = reinterpret_cast<uint4*>(g_probs + (size_t)c * ROWS_P * LS);
        const uint4 z4 = make_uint4(0u, 0u, 0u, 0u);
        for (int j = lane; j < LS / 8; j += 32) gr[j] = z4;
    }
    if (i == L - 1) {
        uint4* gr = reinterpret_cast<uint4*>(
            g_probs + ((size_t)c * ROWS_P + (size_t)(L + 1)) * LS);
        const uint4 z4 = make_uint4(0u, 0u, 0u, 0u);
        for (int j = lane; j < LS / 8; j += 32) gr[j] = z4;
    }
}

// ---------------------------------------------------------------------------
// Kernel 2: grouped 3x3 conv via PACKED f32x2 FMA, channel-pair interleaved.
// SMEM planes hold float2 {u_even[col], u_odd[col]} -> window operands arrive
// PRE-PACKED from LDS.128 (zero pack MOVs); weights pre-packed {w_e,w_o}.
// 576 FFMA2/thread (vs 1152 FFMA). Two output rows per block.
// plane col p holds jj = j0 - 5 + p; windows: p = 4*tid + 4 + m, m=0..5.
// FIX (R12): bias must be in EVERY column's accumulator, not just q=0.
// grid = (4 tiles of 512, L/2 row-pairs, 4 groups), 128 threads.
// ---------------------------------------------------------------------------
__global__ void __launch_bounds__(128, 4) conv3x3_group(const float* __restrict__ weight,
                                                        const float* __restrict__ bias,
                                                        float* __restrict__ out) {
    const int g   = blockIdx.z;
    const int i0  = blockIdx.y * 2;
    const int j0  = blockIdx.x * 512;
    const int tid = threadIdx.x;

    if (j0 > i0 + 1) {  // both rows entirely above diagonal -> zeros
        const float4 z4 = make_float4(0.f, 0.f, 0.f, 0.f);
#pragma unroll
        for (int ro = 0; ro < 2; ro++)
#pragma unroll
            for (int co = 0; co < 4; co++) {
                size_t o = ((size_t)(g * 4 + co) * L + (size_t)(i0 + ro)) * L
                         + (size_t)(j0 + tid * 4);
                *reinterpret_cast<float4*>(out + o) = z4;
            }
        return;
    }

    __shared__ float2 s_p[8][522];   // [pair*4 + r][col p], 33.4 KB
    __shared__ float2 s_w2[72];      // {w_even, w_odd}: [co*18 + pair*9 + kh*3 + kw]
    __shared__ float  s_b[4];

    if (tid < 72) {
        int co = tid / 18, rem = tid % 18;
        int pp = rem / 9, t9 = rem % 9;
        const float* wg = weight + g * 144 + co * 36;
        s_w2[tid] = make_float2(wg[(2 * pp) * 9 + t9], wg[(2 * pp + 1) * 9 + t9]);
    }
    if (tid < 4) s_b[tid] = bias[g * 4 + tid];

    // staging: chunk c covers gmem jj = j0-4+4c -> plane cols p = 4c+1..4c+4
    // as interleaved {even, odd}. 130 chunks per pair-plane.
#pragma unroll
    for (int pp = 0; pp < 2; pp++) {
#pragma unroll
        for (int r = 0; r < 4; r++) {
            const int chA = g * 4 + 2 * pp;
            const uint2* srcA = reinterpret_cast<const uint2*>(
                g_probs + ((size_t)chA * ROWS_P + (size_t)(i0 + r)) * LS + (size_t)j0);
            const uint2* srcB = reinterpret_cast<const uint2*>(
                g_probs + ((size_t)(chA + 1) * ROWS_P + (size_t)(i0 + r)) * LS + (size_t)j0);
            float2* pl = &s_p[pp * 4 + r][0];
#pragma unroll 1
            for (int c = tid; c < 130; c += 128) {
                uint2 va = srcA[c];
                uint2 vb = srcB[c];
                float2 a01 = __half22float2(*reinterpret_cast<__half2*>(&va.x));
                float2 a23 = __half22float2(*reinterpret_cast<__half2*>(&va.y));
                float2 b01 = __half22float2(*reinterpret_cast<__half2*>(&vb.x));
                float2 b23 = __half22float2(*reinterpret_cast<__half2*>(&vb.y));
                pl[4 * c + 1] = make_float2(a01.x, b01.x);
                *reinterpret_cast<float4*>(&pl[4 * c + 2]) =
                    make_float4(a01.y, b01.y, a23.x, b23.x);
                pl[4 * c + 4] = make_float2(a23.y, b23.y);
            }
        }
    }
    __syncthreads();

    // packed accumulators {partial_even, partial_odd}; EVERY column gets bias
    unsigned long long acc[2][4][4];
#pragma unroll
    for (int ro = 0; ro < 2; ro++)
#pragma unroll
        for (int co = 0; co < 4; co++) {
            unsigned long long b0 = pk2(s_b[co], 0.f);
            acc[ro][co][0] = b0;
            acc[ro][co][1] = b0;
            acc[ro][co][2] = b0;
            acc[ro][co][3] = b0;
        }

    const int pb = 4 * tid + 4;   // window base col

#pragma unroll
    for (int pp = 0; pp < 2; pp++) {
        // pre-packed windows: Wm[r][m] = {u_even[jj], u_odd[jj]}, m=0..5
        unsigned long long Wm[4][6];
#pragma unroll
        for (int r = 0; r < 4; r++) {
            const float2* pl = &s_p[pp * 4 + r][0];
            ulonglong2 w01 = *reinterpret_cast<const ulonglong2*>(&pl[pb + 0]);
            ulonglong2 w23 = *reinterpret_cast<const ulonglong2*>(&pl[pb + 2]);
            ulonglong2 w45 = *reinterpret_cast<const ulonglong2*>(&pl[pb + 4]);
            Wm[r][0] = w01.x; Wm[r][1] = w01.y;
            Wm[r][2] = w23.x; Wm[r][3] = w23.y;
            Wm[r][4] = w45.x; Wm[r][5] = w45.y;
        }
#pragma unroll
        for (int ro = 0; ro < 2; ro++) {
#pragma unroll
            for (int kh = 0; kh < 3; kh++) {
                const unsigned long long* v = Wm[ro + kh];
#pragma unroll
                for (int co = 0; co < 4; co++) {
                    const float2* wb = &s_w2[co * 18 + pp * 9 + kh * 3];
                    unsigned long long w0 = *reinterpret_cast<const unsigned long long*>(&wb[0]);
                    unsigned long long w1 = *reinterpret_cast<const unsigned long long*>(&wb[1]);
                    unsigned long long w2 = *reinterpret_cast<const unsigned long long*>(&wb[2]);
                    fma2(acc[ro][co][0], v[0], w0);
                    fma2(acc[ro][co][0], v[1], w1);
                    fma2(acc[ro][co][0], v[2], w2);
                    fma2(acc[ro][co][1], v[1], w0);
                    fma2(acc[ro][co][1], v[2], w1);
                    fma2(acc[ro][co][1], v[3], w2);
                    fma2(acc[ro][co][2], v[2], w0);
                    fma2(acc[ro][co][2], v[3], w1);
                    fma2(acc[ro][co][2], v[4], w2);
                    fma2(acc[ro][co][3], v[3], w0);
                    fma2(acc[ro][co][3], v[4], w1);
                    fma2(acc[ro][co][3], v[5], w2);
                }
            }
        }
    }

    const int colb = j0 + tid * 4;
#pragma unroll
    for (int ro = 0; ro < 2; ro++) {
        const int ii = i0 + ro;
#pragma unroll
        for (int co = 0; co < 4; co++) {
            float lo, hi;
            float4 r4;
            upk2(acc[ro][co][0], lo, hi); r4.x = lo + hi;
            upk2(acc[ro][co][1], lo, hi); r4.y = lo + hi;
            upk2(acc[ro][co][2], lo, hi); r4.z = lo + hi;
            upk2(acc[ro][co][3], lo, hi); r4.w = lo + hi;
            r4.x = (colb + 0 <= ii) ? r4.x : 0.f;
            r4.y = (colb + 1 <= ii) ? r4.y : 0.f;
            r4.z = (colb + 2 <= ii) ? r4.z : 0.f;
            r4.w = (colb + 3 <= ii) ? r4.w : 0.f;
            size_t o = ((size_t)(g * 4 + co) * L + (size_t)ii) * L + (size_t)colb;
            *reinterpret_cast<float4*>(out + o) = r4;
        }
    }
}

extern "C" void kernel_launch(void* const* d_in, const int* in_sizes, int n_in,
                              void* d_out, int out_size) {
    const float* scores = (const float*)d_in[0];
    const float* weight = (const float*)d_in[1];
    const float* bias   = (const float*)d_in[2];
    float* out = (float*)d_out;

    sparsemax_rows<<<dim3(L / 8, CIN), 256>>>(scores);
    conv3x3_group<<<dim3(L / 512, L / 2, GROUPS), 128>>>(weight, bias, out);
}